// round 4
// baseline (speedup 1.0000x reference)
#include <cuda_runtime.h>
#include <cuda_fp16.h>
#include <math.h>

#define N_IN   128
#define NLAY   6
#define N_H    320
#define DEG    32
#define N_OUT  18
#define BATCH  8192
#define BT     64            // batch rows per CTA (2 per lane via half2)
#define PAIRS  32            // row-pairs per tile == lanes
#define SMEM_NODES 1728      // N_IN + 5*N_H kept in shared
#define NTILES (BATCH / BT)  // 128 CTAs, single wave
#define NWARPS 32
#define NTHREADS (NWARPS * 32)   // 1024
#define GSZ    32            // neurons per staged group (== NWARPS)
#define NGRP   (N_H / GSZ)   // 10 groups per layer
#define SWORDS (GSZ * DEG)   // 1024 stage words (1 per thread)
#define HWORDS (N_OUT * DEG) // 576 head stage words

// Layer-5 activations (nodes [1728,2048)); head re-gathers them from global.
__device__ __half2 g_scratch[(size_t)NTILES * N_H * PAIRS];

struct SMem {
    __half2 acts[SMEM_NODES * PAIRS];  // 221,184 B node-major, pair = lane
    int     sidx[SWORDS];              //   4,096 B idx stage
    __half2 sw  [SWORDS];              //   4,096 B weight stage, packed (w,w)
};                                      // 229,376 B total

__global__ void __launch_bounds__(NTHREADS, 1)
policy_kernel(const float* __restrict__ obs,      // [BATCH, N_IN]
              const int*   __restrict__ hid_src,  // [NLAY, N_H, DEG]
              const float* __restrict__ hid_w,    // [NLAY, N_H, DEG]
              const float* __restrict__ hid_b,    // [NLAY, N_H]
              const int*   __restrict__ out_src,  // [N_OUT, DEG]
              const float* __restrict__ out_w,    // [N_OUT, DEG]
              const float* __restrict__ out_b,    // [N_OUT]
              float*       __restrict__ out)      // [BATCH, N_OUT]
{
    extern __shared__ char raw[];
    SMem* s = (SMem*)raw;
    const int tid  = threadIdx.x;
    const int lane = tid & 31;
    const int warp = tid >> 5;
    const int tile = blockIdx.x;

    // ---- obs -> node-major half2 smem. Lane p owns batch rows (2p, 2p+1).
    {
        const int r0 = tile * BT + 2 * lane;
        const float4* o0 = (const float4*)(obs + (size_t)r0 * N_IN);
        const float4* o1 = (const float4*)(obs + (size_t)(r0 + 1) * N_IN);
        const int q = warp;                  // 32 warps cover N_IN/4 quads
        float4 a = o0[q], b = o1[q];
        s->acts[(q * 4 + 0) * PAIRS + lane] = __floats2half2_rn(a.x, b.x);
        s->acts[(q * 4 + 1) * PAIRS + lane] = __floats2half2_rn(a.y, b.y);
        s->acts[(q * 4 + 2) * PAIRS + lane] = __floats2half2_rn(a.z, b.z);
        s->acts[(q * 4 + 3) * PAIRS + lane] = __floats2half2_rn(a.w, b.w);
    }

    __half2* __restrict__ sa  = s->acts + lane;
    __half2* __restrict__ scr = g_scratch + (size_t)tile * (N_H * PAIRS) + lane;

    // ---- Preload group (l=0, g=0) into the stage.
    s->sidx[tid] = hid_src[tid];
    s->sw  [tid] = __float2half2_rn(hid_w[tid]);   // (w,w) packed
    __syncthreads();

    int pidx = 0; __half2 pw = __float2half2_rn(0.f);  // register double-buffer
    for (int l = 0; l < NLAY; l++) {
        const float* bl = hid_b + l * N_H;
        for (int g = 0; g < NGRP; g++) {
            // ---- prefetch next stage words into registers (overlaps compute)
            const bool lastg = (g == NGRP - 1);
            if (!lastg || l + 1 < NLAY) {
                const int base = lastg ? (l + 1) * N_H * DEG
                                       : (l * N_H + (g + 1) * GSZ) * DEG;
                pidx = hid_src[base + tid];
                pw   = __float2half2_rn(hid_w[base + tid]);
            } else if (tid < HWORDS) {       // head stage
                pidx = out_src[tid];
                pw   = __float2half2_rn(out_w[tid]);
            }

            // ---- compute: warp = one neuron x 64 batch rows (HFMA2 path)
            const int n = g * GSZ + warp;
            const int4*  ip = (const int4*) (s->sidx + warp * DEG);  // LDS.128 bcast
            const uint4* wp = (const uint4*)(s->sw   + warp * DEG);  // LDS.128 bcast
            __half2 acc[8];
            #pragma unroll
            for (int k = 0; k < 8; k++) acc[k] = __floats2half2_rn(0.f, 0.f);
            #pragma unroll
            for (int c = 0; c < DEG / 4; c++) {
                const int4  i4 = ip[c];
                const uint4 w4 = wp[c];
                const int k = (c & 1) * 4;   // 8 chains of 4 terms each
                acc[k + 0] = __hfma2(sa[i4.x * PAIRS], *(const __half2*)&w4.x, acc[k + 0]);
                acc[k + 1] = __hfma2(sa[i4.y * PAIRS], *(const __half2*)&w4.y, acc[k + 1]);
                acc[k + 2] = __hfma2(sa[i4.z * PAIRS], *(const __half2*)&w4.z, acc[k + 2]);
                acc[k + 3] = __hfma2(sa[i4.w * PAIRS], *(const __half2*)&w4.w, acc[k + 3]);
            }
            // fp32 epilogue
            float2 f0 = __half22float2(acc[0]), f1 = __half22float2(acc[1]);
            float2 f2 = __half22float2(acc[2]), f3 = __half22float2(acc[3]);
            float2 f4 = __half22float2(acc[4]), f5 = __half22float2(acc[5]);
            float2 f6 = __half22float2(acc[6]), f7 = __half22float2(acc[7]);
            const float bb = bl[n];
            const float sl = (((f0.x + f1.x) + (f2.x + f3.x)) +
                              ((f4.x + f5.x) + (f6.x + f7.x))) + bb;
            const float sh = (((f0.y + f1.y) + (f2.y + f3.y)) +
                              ((f4.y + f5.y) + (f6.y + f7.y))) + bb;
            const __half2 hv = __floats2half2_rn(tanhf(sl), tanhf(sh));
            if (l < NLAY - 1) sa [(N_IN + l * N_H + n) * PAIRS] = hv;  // STS
            else              scr[n * PAIRS] = hv;                     // STG

            __syncthreads();                 // all stage reads done
            if (l + 1 < NLAY || !lastg || tid < HWORDS) {
                s->sidx[tid] = pidx;         // publish next stage
                s->sw  [tid] = pw;
            }
            __syncthreads();                 // stage + prev acts ready
        }
    }

    // ---- output head: 18 neurons (warps 0..17); sources may hit scratch.
    if (warp < N_OUT) {
        const int o = warp;
        const int4*  ip = (const int4*) (s->sidx + o * DEG);
        const uint4* wp = (const uint4*)(s->sw   + o * DEG);
        __half2 acc[8];
        #pragma unroll
        for (int k = 0; k < 8; k++) acc[k] = __floats2half2_rn(0.f, 0.f);
        #pragma unroll
        for (int c = 0; c < DEG / 4; c++) {
            const int4  i4 = ip[c];
            const uint4 w4 = wp[c];
            const int k = (c & 1) * 4;
            #define GATH(II, WW, KK) { const int ii = (II);                           \
                const __half2 v = (ii < SMEM_NODES) ? sa[ii * PAIRS]                  \
                                                    : scr[(ii - SMEM_NODES) * PAIRS]; \
                acc[KK] = __hfma2(v, *(const __half2*)&(WW), acc[KK]); }
            GATH(i4.x, w4.x, k + 0); GATH(i4.y, w4.y, k + 1);
            GATH(i4.z, w4.z, k + 2); GATH(i4.w, w4.w, k + 3);
            #undef GATH
        }
        float2 f0 = __half22float2(acc[0]), f1 = __half22float2(acc[1]);
        float2 f2 = __half22float2(acc[2]), f3 = __half22float2(acc[3]);
        float2 f4 = __half22float2(acc[4]), f5 = __half22float2(acc[5]);
        float2 f6 = __half22float2(acc[6]), f7 = __half22float2(acc[7]);
        const float bo = out_b[o];
        const float sl = (((f0.x + f1.x) + (f2.x + f3.x)) +
                          ((f4.x + f5.x) + (f6.x + f7.x))) + bo;
        const float sh = (((f0.y + f1.y) + (f2.y + f3.y)) +
                          ((f4.y + f5.y) + (f6.y + f7.y))) + bo;
        const int r0 = tile * BT + 2 * lane;
        out[(size_t)r0       * N_OUT + o] = tanhf(sl);
        out[(size_t)(r0 + 1) * N_OUT + o] = tanhf(sh);
    }
}

extern "C" void kernel_launch(void* const* d_in, const int* in_sizes, int n_in,
                              void* d_out, int out_size)
{
    const float* obs     = (const float*)d_in[0];
    const int*   hid_src = (const int*)  d_in[1];
    const float* hid_w   = (const float*)d_in[2];
    const float* hid_b   = (const float*)d_in[3];
    const int*   out_src = (const int*)  d_in[4];
    const float* out_w   = (const float*)d_in[5];
    const float* out_b   = (const float*)d_in[6];
    float*       out     = (float*)d_out;

    const size_t smem = sizeof(SMem);  // 229,376 B
    cudaFuncSetAttribute(policy_kernel,
                         cudaFuncAttributeMaxDynamicSharedMemorySize, (int)smem);
    policy_kernel<<<NTILES, NTHREADS, smem>>>(obs, hid_src, hid_w, hid_b,
                                              out_src, out_w, out_b, out);
}

// round 5
// speedup vs baseline: 1.6033x; 1.6033x over previous
#include <cuda_runtime.h>
#include <cuda_fp16.h>
#include <math.h>

#define N_IN   128
#define NLAY   6
#define N_H    320
#define DEG    32
#define N_OUT  18
#define BATCH  8192
#define BT     64            // batch rows per CTA (2 per lane via half2)
#define PAIRS  32            // row-pairs per tile == lanes
#define SMEM_NODES 1728      // N_IN + 5*N_H kept in shared
#define NTILES (BATCH / BT)  // 128 CTAs, single wave
#define NWARPS 32
#define NTHREADS (NWARPS * 32)   // 1024
#define GSZ    32            // neurons per staged group (== NWARPS)
#define NGROUPS (NLAY * N_H / GSZ)   // 60 groups total
#define LASTL_M (5 * (N_H / GSZ))    // m >= 50 -> layer 5 (scratch store)
#define SWORDS (GSZ * DEG)   // 1024 stage words (1 per thread)
#define HWORDS (N_OUT * DEG) // 576 head stage words

// Layer-5 activations (nodes [1728,2048)); head re-gathers them from global.
__device__ __half2 g_scratch[(size_t)NTILES * N_H * PAIRS];

struct SMem {
    __half2 acts[SMEM_NODES * PAIRS];  // 221,184 B node-major, pair = lane
    int     sidx[SWORDS];              //   4,096 B idx stage
    __half2 sw  [SWORDS];              //   4,096 B weight stage, packed (w,w)
};                                      // 229,376 B total

__global__ void __launch_bounds__(NTHREADS, 1)
policy_kernel(const float* __restrict__ obs,      // [BATCH, N_IN]
              const int*   __restrict__ hid_src,  // [NLAY, N_H, DEG]
              const float* __restrict__ hid_w,    // [NLAY, N_H, DEG]
              const float* __restrict__ hid_b,    // [NLAY*N_H] flat
              const int*   __restrict__ out_src,  // [N_OUT, DEG]
              const float* __restrict__ out_w,    // [N_OUT, DEG]
              const float* __restrict__ out_b,    // [N_OUT]
              float*       __restrict__ out)      // [BATCH, N_OUT]
{
    extern __shared__ char raw[];
    SMem* s = (SMem*)raw;
    const int tid  = threadIdx.x;
    const int lane = tid & 31;
    const int warp = tid >> 5;
    const int tile = blockIdx.x;

    // ---- obs -> node-major half2 smem. Lane p owns batch rows (2p, 2p+1).
    {
        const int r0 = tile * BT + 2 * lane;
        const float4* o0 = (const float4*)(obs + (size_t)r0 * N_IN);
        const float4* o1 = (const float4*)(obs + (size_t)(r0 + 1) * N_IN);
        const int q = warp;                  // 32 warps cover N_IN/4 quads
        float4 a = o0[q], b = o1[q];
        s->acts[(q * 4 + 0) * PAIRS + lane] = __floats2half2_rn(a.x, b.x);
        s->acts[(q * 4 + 1) * PAIRS + lane] = __floats2half2_rn(a.y, b.y);
        s->acts[(q * 4 + 2) * PAIRS + lane] = __floats2half2_rn(a.z, b.z);
        s->acts[(q * 4 + 3) * PAIRS + lane] = __floats2half2_rn(a.w, b.w);
    }

    __half2* __restrict__ sa  = s->acts + lane;
    __half2* __restrict__ scr = g_scratch + (size_t)tile * (N_H * PAIRS) + lane;

    // ---- Preload group m=0 into the stage.
    s->sidx[tid] = hid_src[tid];
    s->sw  [tid] = __float2half2_rn(hid_w[tid]);   // (w,w) packed
    __syncthreads();

    int off = SWORDS;                     // word offset of group m+1
    int pidx = 0; __half2 pw = __floats2half2_rn(0.f, 0.f);

    for (int m = 0; m < NGROUPS; m++) {
        // ---- prefetch next stage words into registers (overlaps compute)
        if (m + 1 < NGROUPS) {
            pidx = hid_src[off + tid];
            pw   = __float2half2_rn(hid_w[off + tid]);
        } else if (tid < HWORDS) {        // head stage
            pidx = out_src[tid];
            pw   = __float2half2_rn(out_w[tid]);
        }
        off += SWORDS;

        // ---- compute: warp = one neuron x 64 batch rows (HFMA2 path)
        const int4*  ip = (const int4*) (s->sidx + warp * DEG);  // LDS.128 bcast
        const uint4* wp = (const uint4*)(s->sw   + warp * DEG);  // LDS.128 bcast
        __half2 acc[8];
        #pragma unroll
        for (int k = 0; k < 8; k++) acc[k] = __floats2half2_rn(0.f, 0.f);
        #pragma unroll
        for (int c = 0; c < DEG / 4; c++) {
            const int4  i4 = ip[c];
            const uint4 w4 = wp[c];
            const int k = (c & 1) * 4;    // 8 chains x 4 terms
            acc[k + 0] = __hfma2(sa[i4.x * PAIRS], *(const __half2*)&w4.x, acc[k + 0]);
            acc[k + 1] = __hfma2(sa[i4.y * PAIRS], *(const __half2*)&w4.y, acc[k + 1]);
            acc[k + 2] = __hfma2(sa[i4.z * PAIRS], *(const __half2*)&w4.z, acc[k + 2]);
            acc[k + 3] = __hfma2(sa[i4.w * PAIRS], *(const __half2*)&w4.w, acc[k + 3]);
        }
        // fp32 epilogue: sequential convert-accumulate (2 live floats, not 16)
        const float bb = hid_b[m * GSZ + warp];
        float sl = bb, sh = bb;
        #pragma unroll
        for (int k = 0; k < 8; k++) {
            const float2 f = __half22float2(acc[k]);
            sl += f.x; sh += f.y;
        }
        const __half2 hv = __floats2half2_rn(tanhf(sl), tanhf(sh));
        const int node = N_IN + m * GSZ + warp;
        if (m < LASTL_M) sa [node * PAIRS] = hv;                 // STS
        else             scr[(node - SMEM_NODES) * PAIRS] = hv;  // coalesced STG

        __syncthreads();                  // all stage reads done
        if (m + 1 < NGROUPS || tid < HWORDS) {
            s->sidx[tid] = pidx;          // publish next stage
            s->sw  [tid] = pw;
        }
        __syncthreads();                  // stage + prev acts ready
    }

    // ---- output head: 18 neurons (warps 0..17); sources may hit scratch.
    if (warp < N_OUT) {
        const int4*  ip = (const int4*) (s->sidx + warp * DEG);
        const uint4* wp = (const uint4*)(s->sw   + warp * DEG);
        __half2 acc[8];
        #pragma unroll
        for (int k = 0; k < 8; k++) acc[k] = __floats2half2_rn(0.f, 0.f);
        #pragma unroll
        for (int c = 0; c < DEG / 4; c++) {
            const int4  i4 = ip[c];
            const uint4 w4 = wp[c];
            const int k = (c & 1) * 4;
            #define GATH(II, WW, KK) { const int ii = (II);                           \
                const __half2 v = (ii < SMEM_NODES) ? sa[ii * PAIRS]                  \
                                                    : scr[(ii - SMEM_NODES) * PAIRS]; \
                acc[KK] = __hfma2(v, *(const __half2*)&(WW), acc[KK]); }
            GATH(i4.x, w4.x, k + 0); GATH(i4.y, w4.y, k + 1);
            GATH(i4.z, w4.z, k + 2); GATH(i4.w, w4.w, k + 3);
            #undef GATH
        }
        const float bo = out_b[warp];
        float sl = bo, sh = bo;
        #pragma unroll
        for (int k = 0; k < 8; k++) {
            const float2 f = __half22float2(acc[k]);
            sl += f.x; sh += f.y;
        }
        const int r0 = tile * BT + 2 * lane;
        out[(size_t)r0       * N_OUT + warp] = tanhf(sl);
        out[(size_t)(r0 + 1) * N_OUT + warp] = tanhf(sh);
    }
}

extern "C" void kernel_launch(void* const* d_in, const int* in_sizes, int n_in,
                              void* d_out, int out_size)
{
    const float* obs     = (const float*)d_in[0];
    const int*   hid_src = (const int*)  d_in[1];
    const float* hid_w   = (const float*)d_in[2];
    const float* hid_b   = (const float*)d_in[3];
    const int*   out_src = (const int*)  d_in[4];
    const float* out_w   = (const float*)d_in[5];
    const float* out_b   = (const float*)d_in[6];
    float*       out     = (float*)d_out;

    const size_t smem = sizeof(SMem);  // 229,376 B
    cudaFuncSetAttribute(policy_kernel,
                         cudaFuncAttributeMaxDynamicSharedMemorySize, (int)smem);
    policy_kernel<<<NTILES, NTHREADS, smem>>>(obs, hid_src, hid_w, hid_b,
                                              out_src, out_w, out_b, out);
}